// round 4
// baseline (speedup 1.0000x reference)
#include <cuda_runtime.h>
#include <math.h>

#define NPTS 65536
#define NN1  16384
#define NN2  8192
#define KNN  16

typedef unsigned long long u64;

__device__ __forceinline__ u64 pk2(float lo, float hi) {
    u64 r; asm("mov.b64 %0,{%1,%2};" : "=l"(r) : "f"(lo), "f"(hi)); return r;
}
__device__ __forceinline__ u64 pk1(float v) { return pk2(v, v); }
__device__ __forceinline__ float2 upk(u64 v) {
    float2 f; asm("mov.b64 {%0,%1},%2;" : "=f"(f.x), "=f"(f.y) : "l"(v)); return f;
}
__device__ __forceinline__ u64 ff2(u64 a, u64 b, u64 c) {
    u64 d; asm("fma.rn.f32x2 %0,%1,%2,%3;" : "=l"(d) : "l"(a), "l"(b), "l"(c)); return d;
}
__device__ __forceinline__ u64 add2(u64 a, u64 b) {
    u64 d; asm("add.rn.f32x2 %0,%1,%2;" : "=l"(d) : "l"(a), "l"(b)); return d;
}

// Intermediate activations
__device__ float g_h [NPTS * 32];
__device__ float g_h1[(size_t)NN1 * 64];
__device__ float g_h2[(size_t)NN2 * 128];

// ---------------------------------------------------------------------------
// down: h = relu(x @ W_down + b_down)   [65536,64]@[64,32]
// ---------------------------------------------------------------------------
__global__ void __launch_bounds__(256)
down_kernel(const float* __restrict__ x,
            const float* __restrict__ W,
            const float* __restrict__ b) {
    __shared__ float sW[64 * 32];
    __shared__ float sb[32];
    int tid = threadIdx.x;
    for (int i = tid; i < 64 * 32; i += 256) sW[i] = W[i];
    if (tid < 32) sb[tid] = b[tid];
    __syncthreads();

    int p = blockIdx.x * 256 + tid;

    float xr[64];
    const float4* xp = (const float4*)(x + (size_t)p * 64);
#pragma unroll
    for (int i = 0; i < 16; i++) {
        float4 v = xp[i];
        xr[4*i+0] = v.x; xr[4*i+1] = v.y; xr[4*i+2] = v.z; xr[4*i+3] = v.w;
    }
    u64 acc[16];
#pragma unroll
    for (int j = 0; j < 16; j++) acc[j] = pk2(sb[2*j], sb[2*j+1]);
#pragma unroll 4
    for (int i = 0; i < 64; i++) {
        u64 xi = pk1(xr[i]);
        const u64* wr = (const u64*)&sW[i * 32];
#pragma unroll
        for (int j = 0; j < 16; j++) acc[j] = ff2(xi, wr[j], acc[j]);
    }
    float* op = &g_h[(size_t)p * 32];
#pragma unroll
    for (int j = 0; j < 16; j++) {
        float2 v = upk(acc[j]);
        op[2*j]   = fmaxf(v.x, 0.f);
        op[2*j+1] = fmaxf(v.y, 0.f);
    }
}

// ---------------------------------------------------------------------------
// conv1: T=8 targets/iter, 512 threads, grid 256, occ 2.
// in-feat 32, rij 32, F=64; 16 edges/target.
// fijT stride 18 (u64-aligned), attT stride 17 (scalar access only).
// ---------------------------------------------------------------------------
#define FT1  18
#define FT1A 17
#define C1_DYN_FLOATS (320 + 4096 + 4096 + 8*64*FT1 + 8*64*FT1A)

__global__ void __launch_bounds__(512, 2)
conv1_kernel(const float* __restrict__ pos,
             const int*   __restrict__ idx1,
             const int*   __restrict__ src1,
             const float* __restrict__ Wpp, const float* __restrict__ bpp,
             const float* __restrict__ Watt, const float* __restrict__ batt,
             const float* __restrict__ Wg,  const float* __restrict__ bg) {
    extern __shared__ float smem[];
    float* sWpp  = smem;                        // 320
    float* sWatt = smem + 320;                  // 4096
    float* sWg   = smem + 4416;                 // 4096
    float* fijT  = smem + 8512;                 // 8*64*18 = 9216  [t][feat][edge]
    float* attT  = smem + 17728;                // 8*64*17 = 8704  [t][o][edge]

    __shared__ float sbpp[32], sbatt[64], sbg[64];
    __shared__ float sm[128], sv[128], sP[128][4];
    __shared__ float aggS[8][64];

    int tid = threadIdx.x;
    for (int i = tid; i < 320; i += 512) sWpp[i] = Wpp[i];
    for (int i = tid; i < 4096; i += 512) { sWatt[i] = Watt[i]; sWg[i] = Wg[i]; }
    if (tid < 32) sbpp[tid] = bpp[tid];
    if (tid < 64) { sbatt[tid] = batt[tid]; sbg[tid] = bg[tid]; }
    __syncthreads();

    for (int t0 = blockIdx.x * 8; t0 < NN1; t0 += gridDim.x * 8) {
        // ---- gather h[src] + point_pos_nn, transposed; rel recomputed inline ----
        {
            int et = tid >> 2, sub = tid & 3;       // 128 edge-targets x 4
            int t = et >> 4, e = et & 15;
            int tgt = t0 + t;
            int pi = idx1[tgt];
            float pix = pos[pi*3+0], piy = pos[pi*3+1], piz = pos[pi*3+2];
            int s = src1[tgt * KNN + e];
            float pjx = pos[s*3+0], pjy = pos[s*3+1], pjz = pos[s*3+2];
            float vx = pix - pjx, vy = piy - pjy, vz = piz - pjz;
            float rel[10];
            rel[0] = pix; rel[1] = piy; rel[2] = piz;
            rel[3] = pjx; rel[4] = pjy; rel[5] = pjz;
            rel[6] = vx;  rel[7] = vy;  rel[8] = vz;
            rel[9] = sqrtf(vx*vx + vy*vy + vz*vz);

            const float4* hp = (const float4*)&g_h[(size_t)s * 32 + sub * 8];
            float4 v0 = hp[0], v1 = hp[1];
            float* dst = &fijT[(t * 64 + sub * 8) * FT1 + e];
            dst[0*FT1] = v0.x; dst[1*FT1] = v0.y; dst[2*FT1] = v0.z; dst[3*FT1] = v0.w;
            dst[4*FT1] = v1.x; dst[5*FT1] = v1.y; dst[6*FT1] = v1.z; dst[7*FT1] = v1.w;
#pragma unroll
            for (int k = 0; k < 8; k++) {
                int o = sub * 8 + k;
                float a = sbpp[o];
#pragma unroll
                for (int i = 0; i < 10; i++) a += rel[i] * sWpp[i * 32 + o];
                fijT[(t * 64 + 32 + o) * FT1 + e] = fmaxf(a, 0.f);
            }
        }
        __syncthreads();

        // ---- att = relu(fij @ Watt + batt): thread = (t8, q16, g4), full i ----
        {
            int t = tid >> 6;              // 0..7
            int q = (tid >> 2) & 15;       // 4 outputs each
            int g = tid & 3;               // edges 4g..4g+3 (2 pairs)
            const float4* W4 = (const float4*)sWatt;
            const float* fb = &fijT[(t * 64) * FT1 + 4 * g];
            u64 acc[8];
#pragma unroll
            for (int j = 0; j < 8; j++) acc[j] = 0ull;
#pragma unroll 4
            for (int i = 0; i < 64; i++) {
                float4 w = W4[i * 16 + q];
                u64 w0 = pk1(w.x), w1 = pk1(w.y), w2 = pk1(w.z), w3 = pk1(w.w);
                const float* fr = fb + i * FT1;
                u64 a0 = *(const u64*)&fr[0], a1 = *(const u64*)&fr[2];
                acc[0] = ff2(a0, w0, acc[0]); acc[1] = ff2(a1, w0, acc[1]);
                acc[2] = ff2(a0, w1, acc[2]); acc[3] = ff2(a1, w1, acc[3]);
                acc[4] = ff2(a0, w2, acc[4]); acc[5] = ff2(a1, w2, acc[5]);
                acc[6] = ff2(a0, w3, acc[6]); acc[7] = ff2(a1, w3, acc[7]);
            }
            float* ab = &attT[(t * 64 + 4 * q) * FT1A + 4 * g];
#pragma unroll
            for (int j = 0; j < 4; j++) {
                float bb = sbatt[4*q + j];
                float2 va = upk(acc[j*2]), vb = upk(acc[j*2+1]);
                ab[j*FT1A + 0] = fmaxf(va.x + bb, 0.f);
                ab[j*FT1A + 1] = fmaxf(va.y + bb, 0.f);
                ab[j*FT1A + 2] = fmaxf(vb.x + bb, 0.f);
                ab[j*FT1A + 3] = fmaxf(vb.y + bb, 0.f);
            }
        }
        __syncthreads();

        // ---- softmax stats per edge over 64 features ----
        {
            int et = tid >> 2, c = tid & 3;
            int t = et >> 4, e = et & 15;
            const float* ac = &attT[(t * 64) * FT1A + e];
            float m = -1e30f;
#pragma unroll 4
            for (int o = c*16; o < c*16+16; o++) m = fmaxf(m, ac[o*FT1A]);
            sP[et][c] = m;
            __syncthreads();
            if (tid < 128)
                sm[tid] = fmaxf(fmaxf(sP[tid][0], sP[tid][1]), fmaxf(sP[tid][2], sP[tid][3]));
            __syncthreads();
            float mm = sm[et];
            float s = 0.f;
#pragma unroll 4
            for (int o = c*16; o < c*16+16; o++) s += __expf(ac[o*FT1A] - mm);
            sP[et][c] = s;
            __syncthreads();
            if (tid < 128)
                sv[tid] = 1.f / (sP[tid][0] + sP[tid][1] + sP[tid][2] + sP[tid][3]);
            __syncthreads();
        }

        // ---- agg[o] = sum_e softmax * fij ----
        {
            int t = tid >> 6, o = tid & 63;
            const float* ar = &attT[(t * 64 + o) * FT1A];
            const float* fr = &fijT[(t * 64 + o) * FT1];
            float a = 0.f;
#pragma unroll
            for (int e = 0; e < 16; e++) {
                int et = t * 16 + e;
                a += __expf(ar[e] - sm[et]) * sv[et] * fr[e];
            }
            aggS[t][o] = a;
        }
        __syncthreads();

        // ---- global: h1 = relu(agg @ Wg + bg), c-split=4 ----
        {
            int t = tid >> 6, q = (tid >> 2) & 15, c = tid & 3;
            u64 s0 = 0ull, s1 = 0ull;
#pragma unroll 4
            for (int ii = 0; ii < 16; ii++) {
                int i = c * 16 + ii;
                u64 xi = pk1(aggS[t][i]);
                s0 = ff2(xi, *(const u64*)&sWg[i*64 + 4*q],     s0);
                s1 = ff2(xi, *(const u64*)&sWg[i*64 + 4*q + 2], s1);
            }
            u64* scr = (u64*)attT;
            if (c) { scr[tid*2] = s0; scr[tid*2+1] = s1; }
            __syncthreads();
            if (c == 0) {
#pragma unroll
                for (int cc = 1; cc < 4; cc++) {
                    s0 = add2(s0, scr[(tid+cc)*2]);
                    s1 = add2(s1, scr[(tid+cc)*2+1]);
                }
                float2 v0 = upk(s0), v1 = upk(s1);
                int o = 4 * q;
                float* op = &g_h1[(size_t)(t0 + t) * 64 + o];
                op[0] = fmaxf(v0.x + sbg[o],   0.f);
                op[1] = fmaxf(v0.y + sbg[o+1], 0.f);
                op[2] = fmaxf(v1.x + sbg[o+2], 0.f);
                op[3] = fmaxf(v1.y + sbg[o+3], 0.f);
            }
            __syncthreads();
        }
    }
}

// ---------------------------------------------------------------------------
// conv2: T=2 targets/iter, 512 threads, grid 256, occ 2.
// Watt in smem; Wg read from global (L2-hot). att uses i-split c=2.
// ---------------------------------------------------------------------------
#define FT2  18
#define FT2A 17
#define C2_DYN_FLOATS (640 + 16384 + 2*128*FT2 + 2*128*FT2A)

__global__ void __launch_bounds__(512, 2)
conv2_kernel(const float* __restrict__ pos,
             const int*   __restrict__ idx1,
             const int*   __restrict__ idx2,
             const int*   __restrict__ src2,
             const float* __restrict__ Wpp, const float* __restrict__ bpp,
             const float* __restrict__ Watt, const float* __restrict__ batt,
             const float* __restrict__ Wg,  const float* __restrict__ bg) {
    extern __shared__ float smem[];
    float* sWpp  = smem;                        // 640
    float* sWatt = smem + 640;                  // 16384
    float* fijT  = smem + 17024;                // 2*128*18 = 4608
    float* attT  = smem + 21632;                // 2*128*17 = 4352

    __shared__ float sbpp[64], sbatt[128], sbg[128];
    __shared__ float sm[32], sv[32], sP[32][16];
    __shared__ float aggS[2][128];

    int tid = threadIdx.x;
    for (int i = tid; i < 640; i += 512) sWpp[i] = Wpp[i];
    for (int i = tid; i < 16384; i += 512) sWatt[i] = Watt[i];
    if (tid < 64)  sbpp[tid] = bpp[tid];
    if (tid < 128) { sbatt[tid] = batt[tid]; sbg[tid] = bg[tid]; }
    __syncthreads();

    for (int t0 = blockIdx.x * 2; t0 < NN2; t0 += gridDim.x * 2) {
        // ---- gather h1[src] (0..63) + pp (64..127), transposed; rel inline ----
        {
            int et = tid >> 4, sub = tid & 15;      // 32 edge-targets x 16
            int t = et >> 4, e = et & 15;
            int tgt = t0 + t;
            int pidx = idx1[idx2[tgt]];
            float pix = pos[pidx*3+0], piy = pos[pidx*3+1], piz = pos[pidx*3+2];
            int s = src2[tgt * KNN + e];
            int pj = idx1[s];
            float pjx = pos[pj*3+0], pjy = pos[pj*3+1], pjz = pos[pj*3+2];
            float vx = pix - pjx, vy = piy - pjy, vz = piz - pjz;
            float rel[10];
            rel[0] = pix; rel[1] = piy; rel[2] = piz;
            rel[3] = pjx; rel[4] = pjy; rel[5] = pjz;
            rel[6] = vx;  rel[7] = vy;  rel[8] = vz;
            rel[9] = sqrtf(vx*vx + vy*vy + vz*vz);

            float4 v = ((const float4*)&g_h1[(size_t)s * 64])[sub];
            float* dst = &fijT[(t * 128 + sub * 4) * FT2 + e];
            dst[0*FT2] = v.x; dst[1*FT2] = v.y; dst[2*FT2] = v.z; dst[3*FT2] = v.w;
#pragma unroll
            for (int k = 0; k < 4; k++) {
                int o = sub * 4 + k;
                float a = sbpp[o];
#pragma unroll
                for (int i = 0; i < 10; i++) a += rel[i] * sWpp[i * 64 + o];
                fijT[(t * 128 + 64 + o) * FT2 + e] = fmaxf(a, 0.f);
            }
        }
        __syncthreads();

        // ---- att: thread = (c2, t2, g4, q32), i-split halves ----
        {
            int c = tid >> 8;                  // i-half
            int t = (tid >> 7) & 1;
            int g = (tid >> 5) & 3;            // edges 4g..4g+3 (2 pairs)
            int q = tid & 31;                  // 4 outputs
            const float4* W4 = (const float4*)sWatt;
            const float* fb = &fijT[(t * 128) * FT2 + 4 * g];
            u64 acc[8];
#pragma unroll
            for (int j = 0; j < 8; j++) acc[j] = 0ull;
#pragma unroll 4
            for (int ii = 0; ii < 64; ii++) {
                int i = c * 64 + ii;
                float4 w = W4[i * 32 + q];
                u64 w0 = pk1(w.x), w1 = pk1(w.y), w2 = pk1(w.z), w3 = pk1(w.w);
                const float* fr = fb + i * FT2;
                u64 a0 = *(const u64*)&fr[0], a1 = *(const u64*)&fr[2];
                acc[0] = ff2(a0, w0, acc[0]); acc[1] = ff2(a1, w0, acc[1]);
                acc[2] = ff2(a0, w1, acc[2]); acc[3] = ff2(a1, w1, acc[3]);
                acc[4] = ff2(a0, w2, acc[4]); acc[5] = ff2(a1, w2, acc[5]);
                acc[6] = ff2(a0, w3, acc[6]); acc[7] = ff2(a1, w3, acc[7]);
            }
            float* ab = &attT[(t * 128 + 4 * q) * FT2A + 4 * g];
            if (c == 1) {
#pragma unroll
                for (int j = 0; j < 4; j++) {
                    float2 va = upk(acc[j*2]), vb = upk(acc[j*2+1]);
                    ab[j*FT2A + 0] = va.x; ab[j*FT2A + 1] = va.y;
                    ab[j*FT2A + 2] = vb.x; ab[j*FT2A + 3] = vb.y;
                }
            }
            __syncthreads();
            if (c == 0) {
#pragma unroll
                for (int j = 0; j < 4; j++) {
                    float bb = sbatt[4*q + j];
                    float2 va = upk(acc[j*2]), vb = upk(acc[j*2+1]);
                    ab[j*FT2A + 0] = fmaxf(ab[j*FT2A + 0] + va.x + bb, 0.f);
                    ab[j*FT2A + 1] = fmaxf(ab[j*FT2A + 1] + va.y + bb, 0.f);
                    ab[j*FT2A + 2] = fmaxf(ab[j*FT2A + 2] + vb.x + bb, 0.f);
                    ab[j*FT2A + 3] = fmaxf(ab[j*FT2A + 3] + vb.y + bb, 0.f);
                }
            }
            __syncthreads();
        }

        // ---- softmax per edge over 128 features ----
        {
            int et = tid >> 4, cc = tid & 15;   // 32 et x 16 chunks of 8
            int t = et >> 4, e = et & 15;
            const float* ac = &attT[(t * 128) * FT2A + e];
            float m = -1e30f;
#pragma unroll
            for (int o = cc*8; o < cc*8+8; o++) m = fmaxf(m, ac[o*FT2A]);
            sP[et][cc] = m;
            __syncthreads();
            if (tid < 32) {
                float mm = sP[tid][0];
#pragma unroll
                for (int k = 1; k < 16; k++) mm = fmaxf(mm, sP[tid][k]);
                sm[tid] = mm;
            }
            __syncthreads();
            float mm = sm[et];
            float s = 0.f;
#pragma unroll
            for (int o = cc*8; o < cc*8+8; o++) s += __expf(ac[o*FT2A] - mm);
            sP[et][cc] = s;
            __syncthreads();
            if (tid < 32) {
                float ss = 0.f;
#pragma unroll
                for (int k = 0; k < 16; k++) ss += sP[tid][k];
                sv[tid] = 1.f / ss;
            }
            __syncthreads();
        }

        // ---- agg ----
        if (tid < 256) {
            int t = tid >> 7, o = tid & 127;
            const float* ar = &attT[(t * 128 + o) * FT2A];
            const float* fr = &fijT[(t * 128 + o) * FT2];
            float a = 0.f;
#pragma unroll
            for (int e = 0; e < 16; e++) {
                int et = t * 16 + e;
                a += __expf(ar[e] - sm[et]) * sv[et] * fr[e];
            }
            aggS[t][o] = a;
        }
        __syncthreads();

        // ---- global: h2 = relu(agg @ Wg + bg), Wg from L2, c-split=8 ----
        {
            int t = (tid >> 8) & 1, q = (tid >> 3) & 31, c = tid & 7;
            u64 s0 = 0ull, s1 = 0ull;
#pragma unroll 4
            for (int ii = 0; ii < 16; ii++) {
                int i = c * 16 + ii;
                u64 xi = pk1(aggS[t][i]);
                float4 w = __ldg((const float4*)&Wg[i*128 + 4*q]);
                s0 = ff2(xi, pk2(w.x, w.y), s0);
                s1 = ff2(xi, pk2(w.z, w.w), s1);
            }
            u64* scr = (u64*)attT;
            if (c) { scr[tid*2] = s0; scr[tid*2+1] = s1; }
            __syncthreads();
            if (c == 0) {
#pragma unroll
                for (int cc = 1; cc < 8; cc++) {
                    s0 = add2(s0, scr[(tid+cc)*2]);
                    s1 = add2(s1, scr[(tid+cc)*2+1]);
                }
                float2 v0 = upk(s0), v1 = upk(s1);
                int o = 4 * q;
                float* op = &g_h2[(size_t)(t0 + t) * 128 + o];
                op[0] = fmaxf(v0.x + sbg[o],   0.f);
                op[1] = fmaxf(v0.y + sbg[o+1], 0.f);
                op[2] = fmaxf(v1.x + sbg[o+2], 0.f);
                op[3] = fmaxf(v1.y + sbg[o+3], 0.f);
            }
            __syncthreads();
        }
    }
}

// ---------------------------------------------------------------------------
// tail: T=16 targets/iter, 512 threads, grid 256, occ 2, split-free.
// thread = (t16, q32): 4 outputs, full i-range.
// ---------------------------------------------------------------------------
#define TAIL_DYN_FLOATS (128*128 + 64*128)

__global__ void __launch_bounds__(512, 2)
tail_kernel(const float* __restrict__ x,
            const int*   __restrict__ idx1,
            const int*   __restrict__ idx2,
            const float* __restrict__ Wup, const float* __restrict__ bup,
            const float* __restrict__ Wsc, const float* __restrict__ bsc,
            float* __restrict__ out) {
    extern __shared__ float smem[];
    float* sWup = smem;               // 16384
    float* sWsc = smem + 16384;       // 8192

    __shared__ float sbup[128], sbsc[128];
    __shared__ float sh2[16 * 128];
    __shared__ float sx[16 * 64];

    int tid = threadIdx.x;
    for (int i = tid; i < 16384; i += 512) sWup[i] = Wup[i];
    for (int i = tid; i < 8192;  i += 512) sWsc[i] = Wsc[i];
    if (tid < 128) { sbup[tid] = bup[tid]; sbsc[tid] = bsc[tid]; }
    __syncthreads();

    for (int t0 = blockIdx.x * 16; t0 < NN2; t0 += gridDim.x * 16) {
#pragma unroll
        for (int k = 0; k < 4; k++)
            sh2[tid + 512*k] = g_h2[(size_t)t0 * 128 + tid + 512*k];
        {
            int t = tid >> 5, f2 = tid & 31;
            int xr = idx1[idx2[t0 + t]];
            const float2* xp = (const float2*)&x[(size_t)xr * 64];
            ((float2*)&sx[t * 64])[f2] = xp[f2];
        }
        __syncthreads();

        int t = tid >> 5;              // 16 targets (warp-uniform)
        int q = tid & 31;              // 4 outputs
        const float* h2r = &sh2[t * 128];
        const float* xrp = &sx[t * 64];

        u64 u0 = 0ull, u1 = 0ull;
#pragma unroll 4
        for (int i = 0; i < 128; i++) {
            u64 xi = pk1(h2r[i]);
            u0 = ff2(xi, *(const u64*)&sWup[i*128 + 4*q],     u0);
            u1 = ff2(xi, *(const u64*)&sWup[i*128 + 4*q + 2], u1);
        }
        u64 s0 = 0ull, s1 = 0ull;
#pragma unroll 4
        for (int i = 0; i < 64; i++) {
            u64 xi = pk1(xrp[i]);
            s0 = ff2(xi, *(const u64*)&sWsc[i*128 + 4*q],     s0);
            s1 = ff2(xi, *(const u64*)&sWsc[i*128 + 4*q + 2], s1);
        }
        float2 a0 = upk(u0), a1 = upk(u1), c0 = upk(s0), c1 = upk(s1);
        int o = 4 * q;
        float* op = &out[(size_t)(t0 + t) * 128 + o];
        op[0] = fmaxf(fmaxf(a0.x + sbup[o],   0.f) + fmaxf(c0.x + sbsc[o],   0.f), 0.f);
        op[1] = fmaxf(fmaxf(a0.y + sbup[o+1], 0.f) + fmaxf(c0.y + sbsc[o+1], 0.f), 0.f);
        op[2] = fmaxf(fmaxf(a1.x + sbup[o+2], 0.f) + fmaxf(c1.x + sbsc[o+2], 0.f), 0.f);
        op[3] = fmaxf(fmaxf(a1.y + sbup[o+3], 0.f) + fmaxf(c1.y + sbsc[o+3], 0.f), 0.f);
        __syncthreads();
    }
}

// ---------------------------------------------------------------------------
extern "C" void kernel_launch(void* const* d_in, const int* in_sizes, int n_in,
                              void* d_out, int out_size) {
    const float* x      = (const float*)d_in[0];
    const float* pos    = (const float*)d_in[1];
    const float* W_down = (const float*)d_in[2];
    const float* b_down = (const float*)d_in[3];
    const float* W_pp1  = (const float*)d_in[4];
    const float* b_pp1  = (const float*)d_in[5];
    const float* W_att1 = (const float*)d_in[6];
    const float* b_att1 = (const float*)d_in[7];
    const float* W_g1   = (const float*)d_in[8];
    const float* b_g1   = (const float*)d_in[9];
    const float* W_pp2  = (const float*)d_in[10];
    const float* b_pp2  = (const float*)d_in[11];
    const float* W_att2 = (const float*)d_in[12];
    const float* b_att2 = (const float*)d_in[13];
    const float* W_g2   = (const float*)d_in[14];
    const float* b_g2   = (const float*)d_in[15];
    const float* W_up   = (const float*)d_in[16];
    const float* b_up   = (const float*)d_in[17];
    const float* W_sc   = (const float*)d_in[18];
    const float* b_sc   = (const float*)d_in[19];
    const int*   idx1   = (const int*)d_in[20];
    const int*   idx2   = (const int*)d_in[21];
    const int*   src1   = (const int*)d_in[22];
    const int*   src2   = (const int*)d_in[24];
    float* out = (float*)d_out;

    cudaFuncSetAttribute(conv1_kernel, cudaFuncAttributeMaxDynamicSharedMemorySize,
                         C1_DYN_FLOATS * (int)sizeof(float));
    cudaFuncSetAttribute(conv2_kernel, cudaFuncAttributeMaxDynamicSharedMemorySize,
                         C2_DYN_FLOATS * (int)sizeof(float));
    cudaFuncSetAttribute(tail_kernel, cudaFuncAttributeMaxDynamicSharedMemorySize,
                         TAIL_DYN_FLOATS * (int)sizeof(float));

    down_kernel<<<NPTS / 256, 256>>>(x, W_down, b_down);
    conv1_kernel<<<256, 512, C1_DYN_FLOATS * sizeof(float)>>>(
        pos, idx1, src1, W_pp1, b_pp1, W_att1, b_att1, W_g1, b_g1);
    conv2_kernel<<<256, 512, C2_DYN_FLOATS * sizeof(float)>>>(
        pos, idx1, idx2, src2, W_pp2, b_pp2, W_att2, b_att2, W_g2, b_g2);
    tail_kernel<<<256, 512, TAIL_DYN_FLOATS * sizeof(float)>>>(
        x, idx1, idx2, W_up, b_up, W_sc, b_sc, out);
}

// round 5
// speedup vs baseline: 1.4482x; 1.4482x over previous
#include <cuda_runtime.h>
#include <math.h>

#define NPTS 65536
#define NN1  16384
#define NN2  8192
#define KNN  16

typedef unsigned long long u64;

__device__ __forceinline__ u64 pk2(float lo, float hi) {
    u64 r; asm("mov.b64 %0,{%1,%2};" : "=l"(r) : "f"(lo), "f"(hi)); return r;
}
__device__ __forceinline__ u64 pk1(float v) { return pk2(v, v); }
__device__ __forceinline__ float2 upk(u64 v) {
    float2 f; asm("mov.b64 {%0,%1},%2;" : "=f"(f.x), "=f"(f.y) : "l"(v)); return f;
}
__device__ __forceinline__ u64 ff2(u64 a, u64 b, u64 c) {
    u64 d; asm("fma.rn.f32x2 %0,%1,%2,%3;" : "=l"(d) : "l"(a), "l"(b), "l"(c)); return d;
}
__device__ __forceinline__ u64 add2(u64 a, u64 b) {
    u64 d; asm("add.rn.f32x2 %0,%1,%2;" : "=l"(d) : "l"(a), "l"(b)); return d;
}

// Intermediate activations (device globals — no allocation allowed)
__device__ float g_h  [NPTS * 32];
__device__ float g_h1 [(size_t)NN1 * 64];
__device__ float g_agg[(size_t)NN2 * 128];   // conv2 pre-global_nn aggregate
__device__ float g_h2 [(size_t)NN2 * 128];

// ---------------------------------------------------------------------------
// down: h = relu(x @ W_down + b_down)   [65536,64]@[64,32]
// ---------------------------------------------------------------------------
__global__ void __launch_bounds__(256)
down_kernel(const float* __restrict__ x,
            const float* __restrict__ W,
            const float* __restrict__ b) {
    __shared__ float sW[64 * 32];
    __shared__ float sb[32];
    int tid = threadIdx.x;
    for (int i = tid; i < 64 * 32; i += 256) sW[i] = W[i];
    if (tid < 32) sb[tid] = b[tid];
    __syncthreads();

    int p = blockIdx.x * 256 + tid;

    float xr[64];
    const float4* xp = (const float4*)(x + (size_t)p * 64);
#pragma unroll
    for (int i = 0; i < 16; i++) {
        float4 v = xp[i];
        xr[4*i+0] = v.x; xr[4*i+1] = v.y; xr[4*i+2] = v.z; xr[4*i+3] = v.w;
    }
    u64 acc[16];
#pragma unroll
    for (int j = 0; j < 16; j++) acc[j] = pk2(sb[2*j], sb[2*j+1]);
#pragma unroll 4
    for (int i = 0; i < 64; i++) {
        u64 xi = pk1(xr[i]);
        const u64* wr = (const u64*)&sW[i * 32];
#pragma unroll
        for (int j = 0; j < 16; j++) acc[j] = ff2(xi, wr[j], acc[j]);
    }
    float* op = &g_h[(size_t)p * 32];
#pragma unroll
    for (int j = 0; j < 16; j++) {
        float2 v = upk(acc[j]);
        op[2*j]   = fmaxf(v.x, 0.f);
        op[2*j+1] = fmaxf(v.y, 0.f);
    }
}

// ---------------------------------------------------------------------------
// conv1: T=8 targets/iter, 512 threads, grid 296 (= 148 SMs x occ 2, balanced)
// ---------------------------------------------------------------------------
#define FT1  18
#define FT1A 17
#define C1_DYN_FLOATS (320 + 4096 + 4096 + 8*64*FT1 + 8*64*FT1A)

__global__ void __launch_bounds__(512, 2)
conv1_kernel(const float* __restrict__ pos,
             const int*   __restrict__ idx1,
             const int*   __restrict__ src1,
             const float* __restrict__ Wpp, const float* __restrict__ bpp,
             const float* __restrict__ Watt, const float* __restrict__ batt,
             const float* __restrict__ Wg,  const float* __restrict__ bg) {
    extern __shared__ float smem[];
    float* sWpp  = smem;                        // 320
    float* sWatt = smem + 320;                  // 4096
    float* sWg   = smem + 4416;                 // 4096
    float* fijT  = smem + 8512;                 // 8*64*18 [t][feat][edge]
    float* attT  = smem + 17728;                // 8*64*17 [t][o][edge]

    __shared__ float sbpp[32], sbatt[64], sbg[64];
    __shared__ float sm[128], sv[128], sP[128][4];
    __shared__ float aggS[8][64];

    int tid = threadIdx.x;
    for (int i = tid; i < 320; i += 512) sWpp[i] = Wpp[i];
    for (int i = tid; i < 4096; i += 512) { sWatt[i] = Watt[i]; sWg[i] = Wg[i]; }
    if (tid < 32) sbpp[tid] = bpp[tid];
    if (tid < 64) { sbatt[tid] = batt[tid]; sbg[tid] = bg[tid]; }
    __syncthreads();

    for (int t0 = blockIdx.x * 8; t0 < NN1; t0 += gridDim.x * 8) {
        // ---- gather h[src] + point_pos_nn, transposed; rel recomputed inline ----
        {
            int et = tid >> 2, sub = tid & 3;
            int t = et >> 4, e = et & 15;
            int tgt = t0 + t;
            int pi = idx1[tgt];
            float pix = pos[pi*3+0], piy = pos[pi*3+1], piz = pos[pi*3+2];
            int s = src1[tgt * KNN + e];
            float pjx = pos[s*3+0], pjy = pos[s*3+1], pjz = pos[s*3+2];
            float vx = pix - pjx, vy = piy - pjy, vz = piz - pjz;
            float rel[10];
            rel[0] = pix; rel[1] = piy; rel[2] = piz;
            rel[3] = pjx; rel[4] = pjy; rel[5] = pjz;
            rel[6] = vx;  rel[7] = vy;  rel[8] = vz;
            rel[9] = sqrtf(vx*vx + vy*vy + vz*vz);

            const float4* hp = (const float4*)&g_h[(size_t)s * 32 + sub * 8];
            float4 v0 = hp[0], v1 = hp[1];
            float* dst = &fijT[(t * 64 + sub * 8) * FT1 + e];
            dst[0*FT1] = v0.x; dst[1*FT1] = v0.y; dst[2*FT1] = v0.z; dst[3*FT1] = v0.w;
            dst[4*FT1] = v1.x; dst[5*FT1] = v1.y; dst[6*FT1] = v1.z; dst[7*FT1] = v1.w;
#pragma unroll
            for (int k = 0; k < 8; k++) {
                int o = sub * 8 + k;
                float a = sbpp[o];
#pragma unroll
                for (int i = 0; i < 10; i++) a += rel[i] * sWpp[i * 32 + o];
                fijT[(t * 64 + 32 + o) * FT1 + e] = fmaxf(a, 0.f);
            }
        }
        __syncthreads();

        // ---- att = relu(fij @ Watt + batt): thread = (t8, q16, g4), full i ----
        {
            int t = tid >> 6;
            int q = (tid >> 2) & 15;
            int g = tid & 3;
            const float4* W4 = (const float4*)sWatt;
            const float* fb = &fijT[(t * 64) * FT1 + 4 * g];
            u64 acc[8];
#pragma unroll
            for (int j = 0; j < 8; j++) acc[j] = 0ull;
#pragma unroll 4
            for (int i = 0; i < 64; i++) {
                float4 w = W4[i * 16 + q];
                u64 w0 = pk1(w.x), w1 = pk1(w.y), w2 = pk1(w.z), w3 = pk1(w.w);
                const float* fr = fb + i * FT1;
                u64 a0 = *(const u64*)&fr[0], a1 = *(const u64*)&fr[2];
                acc[0] = ff2(a0, w0, acc[0]); acc[1] = ff2(a1, w0, acc[1]);
                acc[2] = ff2(a0, w1, acc[2]); acc[3] = ff2(a1, w1, acc[3]);
                acc[4] = ff2(a0, w2, acc[4]); acc[5] = ff2(a1, w2, acc[5]);
                acc[6] = ff2(a0, w3, acc[6]); acc[7] = ff2(a1, w3, acc[7]);
            }
            float* ab = &attT[(t * 64 + 4 * q) * FT1A + 4 * g];
#pragma unroll
            for (int j = 0; j < 4; j++) {
                float bb = sbatt[4*q + j];
                float2 va = upk(acc[j*2]), vb = upk(acc[j*2+1]);
                ab[j*FT1A + 0] = fmaxf(va.x + bb, 0.f);
                ab[j*FT1A + 1] = fmaxf(va.y + bb, 0.f);
                ab[j*FT1A + 2] = fmaxf(vb.x + bb, 0.f);
                ab[j*FT1A + 3] = fmaxf(vb.y + bb, 0.f);
            }
        }
        __syncthreads();

        // ---- softmax stats per edge over 64 features ----
        {
            int et = tid >> 2, c = tid & 3;
            int t = et >> 4, e = et & 15;
            const float* ac = &attT[(t * 64) * FT1A + e];
            float m = -1e30f;
#pragma unroll 4
            for (int o = c*16; o < c*16+16; o++) m = fmaxf(m, ac[o*FT1A]);
            sP[et][c] = m;
            __syncthreads();
            if (tid < 128)
                sm[tid] = fmaxf(fmaxf(sP[tid][0], sP[tid][1]), fmaxf(sP[tid][2], sP[tid][3]));
            __syncthreads();
            float mm = sm[et];
            float s = 0.f;
#pragma unroll 4
            for (int o = c*16; o < c*16+16; o++) s += __expf(ac[o*FT1A] - mm);
            sP[et][c] = s;
            __syncthreads();
            if (tid < 128)
                sv[tid] = 1.f / (sP[tid][0] + sP[tid][1] + sP[tid][2] + sP[tid][3]);
            __syncthreads();
        }

        // ---- agg[o] = sum_e softmax * fij ----
        {
            int t = tid >> 6, o = tid & 63;
            const float* ar = &attT[(t * 64 + o) * FT1A];
            const float* fr = &fijT[(t * 64 + o) * FT1];
            float a = 0.f;
#pragma unroll
            for (int e = 0; e < 16; e++) {
                int et = t * 16 + e;
                a += __expf(ar[e] - sm[et]) * sv[et] * fr[e];
            }
            aggS[t][o] = a;
        }
        __syncthreads();

        // ---- global: h1 = relu(agg @ Wg + bg), c-split=4 ----
        {
            int t = tid >> 6, q = (tid >> 2) & 15, c = tid & 3;
            u64 s0 = 0ull, s1 = 0ull;
#pragma unroll 4
            for (int ii = 0; ii < 16; ii++) {
                int i = c * 16 + ii;
                u64 xi = pk1(aggS[t][i]);
                s0 = ff2(xi, *(const u64*)&sWg[i*64 + 4*q],     s0);
                s1 = ff2(xi, *(const u64*)&sWg[i*64 + 4*q + 2], s1);
            }
            u64* scr = (u64*)attT;
            if (c) { scr[tid*2] = s0; scr[tid*2+1] = s1; }
            __syncthreads();
            if (c == 0) {
#pragma unroll
                for (int cc = 1; cc < 4; cc++) {
                    s0 = add2(s0, scr[(tid+cc)*2]);
                    s1 = add2(s1, scr[(tid+cc)*2+1]);
                }
                float2 v0 = upk(s0), v1 = upk(s1);
                int o = 4 * q;
                float* op = &g_h1[(size_t)(t0 + t) * 64 + o];
                op[0] = fmaxf(v0.x + sbg[o],   0.f);
                op[1] = fmaxf(v0.y + sbg[o+1], 0.f);
                op[2] = fmaxf(v1.x + sbg[o+2], 0.f);
                op[3] = fmaxf(v1.y + sbg[o+3], 0.f);
            }
            __syncthreads();
        }
    }
}

// ---------------------------------------------------------------------------
// conv2: T=2 targets/iter, 512 threads, grid 296. Ends at agg -> g_agg.
// (global_nn matmul moved to gemm2_kernel; no Wg access here.)
// ---------------------------------------------------------------------------
#define FT2  18
#define FT2A 17
#define C2_DYN_FLOATS (640 + 16384 + 2*128*FT2 + 2*128*FT2A)

__global__ void __launch_bounds__(512, 2)
conv2_kernel(const float* __restrict__ pos,
             const int*   __restrict__ idx1,
             const int*   __restrict__ idx2,
             const int*   __restrict__ src2,
             const float* __restrict__ Wpp, const float* __restrict__ bpp,
             const float* __restrict__ Watt, const float* __restrict__ batt) {
    extern __shared__ float smem[];
    float* sWpp  = smem;                        // 640
    float* sWatt = smem + 640;                  // 16384
    float* fijT  = smem + 17024;                // 2*128*18
    float* attT  = smem + 21632;                // 2*128*17

    __shared__ float sbpp[64], sbatt[128];
    __shared__ float sm[32], sv[32], sP[32][16];

    int tid = threadIdx.x;
    for (int i = tid; i < 640; i += 512) sWpp[i] = Wpp[i];
    for (int i = tid; i < 16384; i += 512) sWatt[i] = Watt[i];
    if (tid < 64)  sbpp[tid] = bpp[tid];
    if (tid < 128) sbatt[tid] = batt[tid];
    __syncthreads();

    for (int t0 = blockIdx.x * 2; t0 < NN2; t0 += gridDim.x * 2) {
        // ---- gather h1[src] (0..63) + pp (64..127), transposed; rel inline ----
        {
            int et = tid >> 4, sub = tid & 15;
            int t = et >> 4, e = et & 15;
            int tgt = t0 + t;
            int pidx = idx1[idx2[tgt]];
            float pix = pos[pidx*3+0], piy = pos[pidx*3+1], piz = pos[pidx*3+2];
            int s = src2[tgt * KNN + e];
            int pj = idx1[s];
            float pjx = pos[pj*3+0], pjy = pos[pj*3+1], pjz = pos[pj*3+2];
            float vx = pix - pjx, vy = piy - pjy, vz = piz - pjz;
            float rel[10];
            rel[0] = pix; rel[1] = piy; rel[2] = piz;
            rel[3] = pjx; rel[4] = pjy; rel[5] = pjz;
            rel[6] = vx;  rel[7] = vy;  rel[8] = vz;
            rel[9] = sqrtf(vx*vx + vy*vy + vz*vz);

            float4 v = ((const float4*)&g_h1[(size_t)s * 64])[sub];
            float* dst = &fijT[(t * 128 + sub * 4) * FT2 + e];
            dst[0*FT2] = v.x; dst[1*FT2] = v.y; dst[2*FT2] = v.z; dst[3*FT2] = v.w;
#pragma unroll
            for (int k = 0; k < 4; k++) {
                int o = sub * 4 + k;
                float a = sbpp[o];
#pragma unroll
                for (int i = 0; i < 10; i++) a += rel[i] * sWpp[i * 64 + o];
                fijT[(t * 128 + 64 + o) * FT2 + e] = fmaxf(a, 0.f);
            }
        }
        __syncthreads();

        // ---- att: thread = (c2, t2, g4, q32), i-split halves ----
        {
            int c = tid >> 8;
            int t = (tid >> 7) & 1;
            int g = (tid >> 5) & 3;
            int q = tid & 31;
            const float4* W4 = (const float4*)sWatt;
            const float* fb = &fijT[(t * 128) * FT2 + 4 * g];
            u64 acc[8];
#pragma unroll
            for (int j = 0; j < 8; j++) acc[j] = 0ull;
#pragma unroll 4
            for (int ii = 0; ii < 64; ii++) {
                int i = c * 64 + ii;
                float4 w = W4[i * 32 + q];
                u64 w0 = pk1(w.x), w1 = pk1(w.y), w2 = pk1(w.z), w3 = pk1(w.w);
                const float* fr = fb + i * FT2;
                u64 a0 = *(const u64*)&fr[0], a1 = *(const u64*)&fr[2];
                acc[0] = ff2(a0, w0, acc[0]); acc[1] = ff2(a1, w0, acc[1]);
                acc[2] = ff2(a0, w1, acc[2]); acc[3] = ff2(a1, w1, acc[3]);
                acc[4] = ff2(a0, w2, acc[4]); acc[5] = ff2(a1, w2, acc[5]);
                acc[6] = ff2(a0, w3, acc[6]); acc[7] = ff2(a1, w3, acc[7]);
            }
            float* ab = &attT[(t * 128 + 4 * q) * FT2A + 4 * g];
            if (c == 1) {
#pragma unroll
                for (int j = 0; j < 4; j++) {
                    float2 va = upk(acc[j*2]), vb = upk(acc[j*2+1]);
                    ab[j*FT2A + 0] = va.x; ab[j*FT2A + 1] = va.y;
                    ab[j*FT2A + 2] = vb.x; ab[j*FT2A + 3] = vb.y;
                }
            }
            __syncthreads();
            if (c == 0) {
#pragma unroll
                for (int j = 0; j < 4; j++) {
                    float bb = sbatt[4*q + j];
                    float2 va = upk(acc[j*2]), vb = upk(acc[j*2+1]);
                    ab[j*FT2A + 0] = fmaxf(ab[j*FT2A + 0] + va.x + bb, 0.f);
                    ab[j*FT2A + 1] = fmaxf(ab[j*FT2A + 1] + va.y + bb, 0.f);
                    ab[j*FT2A + 2] = fmaxf(ab[j*FT2A + 2] + vb.x + bb, 0.f);
                    ab[j*FT2A + 3] = fmaxf(ab[j*FT2A + 3] + vb.y + bb, 0.f);
                }
            }
            __syncthreads();
        }

        // ---- softmax per edge over 128 features ----
        {
            int et = tid >> 4, cc = tid & 15;
            int t = et >> 4, e = et & 15;
            const float* ac = &attT[(t * 128) * FT2A + e];
            float m = -1e30f;
#pragma unroll
            for (int o = cc*8; o < cc*8+8; o++) m = fmaxf(m, ac[o*FT2A]);
            sP[et][cc] = m;
            __syncthreads();
            if (tid < 32) {
                float mm = sP[tid][0];
#pragma unroll
                for (int k = 1; k < 16; k++) mm = fmaxf(mm, sP[tid][k]);
                sm[tid] = mm;
            }
            __syncthreads();
            float mm = sm[et];
            float s = 0.f;
#pragma unroll
            for (int o = cc*8; o < cc*8+8; o++) s += __expf(ac[o*FT2A] - mm);
            sP[et][cc] = s;
            __syncthreads();
            if (tid < 32) {
                float ss = 0.f;
#pragma unroll
                for (int k = 0; k < 16; k++) ss += sP[tid][k];
                sv[tid] = 1.f / ss;
            }
            __syncthreads();
        }

        // ---- agg -> global scratch ----
        if (tid < 256) {
            int t = tid >> 7, o = tid & 127;
            const float* ar = &attT[(t * 128 + o) * FT2A];
            const float* fr = &fijT[(t * 128 + o) * FT2];
            float a = 0.f;
#pragma unroll
            for (int e = 0; e < 16; e++) {
                int et = t * 16 + e;
                a += __expf(ar[e] - sm[et]) * sv[et] * fr[e];
            }
            g_agg[(size_t)(t0 + t) * 128 + o] = a;
        }
        __syncthreads();
    }
}

// ---------------------------------------------------------------------------
// gemm2: h2 = relu(g_agg @ Wg + bg)   [8192,128]@[128,128], Wg in smem
// T=16 targets/iter, 512 threads, grid 296, occ 2.
// ---------------------------------------------------------------------------
#define G2_DYN_FLOATS (128*128)

__global__ void __launch_bounds__(512, 2)
gemm2_kernel(const float* __restrict__ Wg, const float* __restrict__ bg) {
    extern __shared__ float smem[];
    float* sWg = smem;                // 16384
    __shared__ float sbg[128];
    __shared__ float sagg[16 * 128];

    int tid = threadIdx.x;
    for (int i = tid; i < 16384; i += 512) sWg[i] = Wg[i];
    if (tid < 128) sbg[tid] = bg[tid];
    __syncthreads();

    for (int t0 = blockIdx.x * 16; t0 < NN2; t0 += gridDim.x * 16) {
#pragma unroll
        for (int k = 0; k < 4; k++)
            sagg[tid + 512*k] = g_agg[(size_t)t0 * 128 + tid + 512*k];
        __syncthreads();

        int t = tid >> 5;              // 16 targets
        int q = tid & 31;              // 4 outputs
        const float* ar = &sagg[t * 128];

        u64 s0 = 0ull, s1 = 0ull;
#pragma unroll 4
        for (int i = 0; i < 128; i++) {
            u64 xi = pk1(ar[i]);
            s0 = ff2(xi, *(const u64*)&sWg[i*128 + 4*q],     s0);
            s1 = ff2(xi, *(const u64*)&sWg[i*128 + 4*q + 2], s1);
        }
        float2 v0 = upk(s0), v1 = upk(s1);
        int o = 4 * q;
        float* op = &g_h2[(size_t)(t0 + t) * 128 + o];
        op[0] = fmaxf(v0.x + sbg[o],   0.f);
        op[1] = fmaxf(v0.y + sbg[o+1], 0.f);
        op[2] = fmaxf(v1.x + sbg[o+2], 0.f);
        op[3] = fmaxf(v1.y + sbg[o+3], 0.f);
        __syncthreads();
    }
}

// ---------------------------------------------------------------------------
// tail: T=16 targets/iter, 512 threads, grid 296, occ 2, split-free.
// ---------------------------------------------------------------------------
#define TAIL_DYN_FLOATS (128*128 + 64*128)

__global__ void __launch_bounds__(512, 2)
tail_kernel(const float* __restrict__ x,
            const int*   __restrict__ idx1,
            const int*   __restrict__ idx2,
            const float* __restrict__ Wup, const float* __restrict__ bup,
            const float* __restrict__ Wsc, const float* __restrict__ bsc,
            float* __restrict__ out) {
    extern __shared__ float smem[];
    float* sWup = smem;               // 16384
    float* sWsc = smem + 16384;       // 8192

    __shared__ float sbup[128], sbsc[128];
    __shared__ float sh2[16 * 128];
    __shared__ float sx[16 * 64];

    int tid = threadIdx.x;
    for (int i = tid; i < 16384; i += 512) sWup[i] = Wup[i];
    for (int i = tid; i < 8192;  i += 512) sWsc[i] = Wsc[i];
    if (tid < 128) { sbup[tid] = bup[tid]; sbsc[tid] = bsc[tid]; }
    __syncthreads();

    for (int t0 = blockIdx.x * 16; t0 < NN2; t0 += gridDim.x * 16) {
#pragma unroll
        for (int k = 0; k < 4; k++)
            sh2[tid + 512*k] = g_h2[(size_t)t0 * 128 + tid + 512*k];
        {
            int t = tid >> 5, f2 = tid & 31;
            int xr = idx1[idx2[t0 + t]];
            const float2* xp = (const float2*)&x[(size_t)xr * 64];
            ((float2*)&sx[t * 64])[f2] = xp[f2];
        }
        __syncthreads();

        int t = tid >> 5;
        int q = tid & 31;
        const float* h2r = &sh2[t * 128];
        const float* xrp = &sx[t * 64];

        u64 u0 = 0ull, u1 = 0ull;
#pragma unroll 4
        for (int i = 0; i < 128; i++) {
            u64 xi = pk1(h2r[i]);
            u0 = ff2(xi, *(const u64*)&sWup[i*128 + 4*q],     u0);
            u1 = ff2(xi, *(const u64*)&sWup[i*128 + 4*q + 2], u1);
        }
        u64 s0 = 0ull, s1 = 0ull;
#pragma unroll 4
        for (int i = 0; i < 64; i++) {
            u64 xi = pk1(xrp[i]);
            s0 = ff2(xi, *(const u64*)&sWsc[i*128 + 4*q],     s0);
            s1 = ff2(xi, *(const u64*)&sWsc[i*128 + 4*q + 2], s1);
        }
        float2 a0 = upk(u0), a1 = upk(u1), c0 = upk(s0), c1 = upk(s1);
        int o = 4 * q;
        float* op = &out[(size_t)(t0 + t) * 128 + o];
        op[0] = fmaxf(fmaxf(a0.x + sbup[o],   0.f) + fmaxf(c0.x + sbsc[o],   0.f), 0.f);
        op[1] = fmaxf(fmaxf(a0.y + sbup[o+1], 0.f) + fmaxf(c0.y + sbsc[o+1], 0.f), 0.f);
        op[2] = fmaxf(fmaxf(a1.x + sbup[o+2], 0.f) + fmaxf(c1.x + sbsc[o+2], 0.f), 0.f);
        op[3] = fmaxf(fmaxf(a1.y + sbup[o+3], 0.f) + fmaxf(c1.y + sbsc[o+3], 0.f), 0.f);
        __syncthreads();
    }
}

// ---------------------------------------------------------------------------
extern "C" void kernel_launch(void* const* d_in, const int* in_sizes, int n_in,
                              void* d_out, int out_size) {
    const float* x      = (const float*)d_in[0];
    const float* pos    = (const float*)d_in[1];
    const float* W_down = (const float*)d_in[2];
    const float* b_down = (const float*)d_in[3];
    const float* W_pp1  = (const float*)d_in[4];
    const float* b_pp1  = (const float*)d_in[5];
    const float* W_att1 = (const float*)d_in[6];
    const float* b_att1 = (const float*)d_in[7];
    const float* W_g1   = (const float*)d_in[8];
    const float* b_g1   = (const float*)d_in[9];
    const float* W_pp2  = (const float*)d_in[10];
    const float* b_pp2  = (const float*)d_in[11];
    const float* W_att2 = (const float*)d_in[12];
    const float* b_att2 = (const float*)d_in[13];
    const float* W_g2   = (const float*)d_in[14];
    const float* b_g2   = (const float*)d_in[15];
    const float* W_up   = (const float*)d_in[16];
    const float* b_up   = (const float*)d_in[17];
    const float* W_sc   = (const float*)d_in[18];
    const float* b_sc   = (const float*)d_in[19];
    const int*   idx1   = (const int*)d_in[20];
    const int*   idx2   = (const int*)d_in[21];
    const int*   src1   = (const int*)d_in[22];
    const int*   src2   = (const int*)d_in[24];
    float* out = (float*)d_out;

    cudaFuncSetAttribute(conv1_kernel, cudaFuncAttributeMaxDynamicSharedMemorySize,
                         C1_DYN_FLOATS * (int)sizeof(float));
    cudaFuncSetAttribute(conv2_kernel, cudaFuncAttributeMaxDynamicSharedMemorySize,
                         C2_DYN_FLOATS * (int)sizeof(float));
    cudaFuncSetAttribute(gemm2_kernel, cudaFuncAttributeMaxDynamicSharedMemorySize,
                         G2_DYN_FLOATS * (int)sizeof(float));
    cudaFuncSetAttribute(tail_kernel, cudaFuncAttributeMaxDynamicSharedMemorySize,
                         TAIL_DYN_FLOATS * (int)sizeof(float));

    down_kernel<<<NPTS / 256, 256>>>(x, W_down, b_down);
    conv1_kernel<<<296, 512, C1_DYN_FLOATS * sizeof(float)>>>(
        pos, idx1, src1, W_pp1, b_pp1, W_att1, b_att1, W_g1, b_g1);
    conv2_kernel<<<296, 512, C2_DYN_FLOATS * sizeof(float)>>>(
        pos, idx1, idx2, src2, W_pp2, b_pp2, W_att2, b_att2);
    gemm2_kernel<<<296, 512, G2_DYN_FLOATS * sizeof(float)>>>(W_g2, b_g2);
    tail_kernel<<<296, 512, TAIL_DYN_FLOATS * sizeof(float)>>>(
        x, idx1, idx2, W_up, b_up, W_sc, b_sc, out);
}

// round 6
// speedup vs baseline: 1.5761x; 1.0883x over previous
#include <cuda_runtime.h>
#include <math.h>

#define NPTS 65536
#define NN1  16384
#define NN2  8192
#define KNN  16

typedef unsigned long long u64;

__device__ __forceinline__ u64 pk2(float lo, float hi) {
    u64 r; asm("mov.b64 %0,{%1,%2};" : "=l"(r) : "f"(lo), "f"(hi)); return r;
}
__device__ __forceinline__ u64 pk1(float v) { return pk2(v, v); }
__device__ __forceinline__ float2 upk(u64 v) {
    float2 f; asm("mov.b64 {%0,%1},%2;" : "=f"(f.x), "=f"(f.y) : "l"(v)); return f;
}
__device__ __forceinline__ u64 ff2(u64 a, u64 b, u64 c) {
    u64 d; asm("fma.rn.f32x2 %0,%1,%2,%3;" : "=l"(d) : "l"(a), "l"(b), "l"(c)); return d;
}
__device__ __forceinline__ u64 add2(u64 a, u64 b) {
    u64 d; asm("add.rn.f32x2 %0,%1,%2;" : "=l"(d) : "l"(a), "l"(b)); return d;
}

// Intermediate activations (device globals — no allocation allowed)
__device__ float g_h  [NPTS * 32];
__device__ float g_h1 [(size_t)NN1 * 64];
__device__ float g_agg[(size_t)NN2 * 128];
__device__ float g_h2 [(size_t)NN2 * 128];

// ---------------------------------------------------------------------------
// down: h = relu(x @ W_down + b_down)   [65536,64]@[64,32]
// ---------------------------------------------------------------------------
__global__ void __launch_bounds__(256)
down_kernel(const float* __restrict__ x,
            const float* __restrict__ W,
            const float* __restrict__ b) {
    __shared__ float sW[64 * 32];
    __shared__ float sb[32];
    int tid = threadIdx.x;
    for (int i = tid; i < 64 * 32; i += 256) sW[i] = W[i];
    if (tid < 32) sb[tid] = b[tid];
    __syncthreads();

    int p = blockIdx.x * 256 + tid;

    float xr[64];
    const float4* xp = (const float4*)(x + (size_t)p * 64);
#pragma unroll
    for (int i = 0; i < 16; i++) {
        float4 v = xp[i];
        xr[4*i+0] = v.x; xr[4*i+1] = v.y; xr[4*i+2] = v.z; xr[4*i+3] = v.w;
    }
    u64 acc[16];
#pragma unroll
    for (int j = 0; j < 16; j++) acc[j] = pk2(sb[2*j], sb[2*j+1]);
#pragma unroll 4
    for (int i = 0; i < 64; i++) {
        u64 xi = pk1(xr[i]);
        const u64* wr = (const u64*)&sW[i * 32];
#pragma unroll
        for (int j = 0; j < 16; j++) acc[j] = ff2(xi, wr[j], acc[j]);
    }
    float* op = &g_h[(size_t)p * 32];
#pragma unroll
    for (int j = 0; j < 16; j++) {
        float2 v = upk(acc[j]);
        op[2*j]   = fmaxf(v.x, 0.f);
        op[2*j+1] = fmaxf(v.y, 0.f);
    }
}

// ---------------------------------------------------------------------------
// conv1: T=8 targets/iter, 512 threads, grid 296, occ 2.
// fijT stride 20 (16B-aligned edge quads), attT stride 17.
// ---------------------------------------------------------------------------
#define FT1  20
#define FT1A 17
#define C1_DYN_FLOATS (320 + 4096 + 4096 + 8*64*FT1 + 8*64*FT1A)

__global__ void __launch_bounds__(512, 2)
conv1_kernel(const float* __restrict__ pos,
             const int*   __restrict__ idx1,
             const int*   __restrict__ src1,
             const float* __restrict__ Wpp, const float* __restrict__ bpp,
             const float* __restrict__ Watt, const float* __restrict__ batt,
             const float* __restrict__ Wg,  const float* __restrict__ bg) {
    extern __shared__ float smem[];
    float* sWpp  = smem;                        // 320
    float* sWatt = smem + 320;                  // 4096
    float* sWg   = smem + 4416;                 // 4096
    float* fijT  = smem + 8512;                 // 8*64*20 [t][feat][edge]
    float* attT  = smem + 8512 + 8*64*FT1;      // 8*64*17 [t][o][edge]

    __shared__ float sbpp[32], sbatt[64], sbg[64];
    __shared__ float sm[128], sv[128];
    __shared__ float aggS[8][64];

    int tid = threadIdx.x;
    for (int i = tid; i < 320; i += 512) sWpp[i] = Wpp[i];
    for (int i = tid; i < 4096; i += 512) { sWatt[i] = Watt[i]; sWg[i] = Wg[i]; }
    if (tid < 32) sbpp[tid] = bpp[tid];
    if (tid < 64) { sbatt[tid] = batt[tid]; sbg[tid] = bg[tid]; }
    __syncthreads();

    for (int t0 = blockIdx.x * 8; t0 < NN1; t0 += gridDim.x * 8) {
        // ---- gather h[src] + point_pos_nn, transposed; rel inline ----
        {
            int et = tid >> 2, sub = tid & 3;
            int t = et >> 4, e = et & 15;
            int tgt = t0 + t;
            int pi = idx1[tgt];
            float pix = pos[pi*3+0], piy = pos[pi*3+1], piz = pos[pi*3+2];
            int s = src1[tgt * KNN + e];
            float pjx = pos[s*3+0], pjy = pos[s*3+1], pjz = pos[s*3+2];
            float vx = pix - pjx, vy = piy - pjy, vz = piz - pjz;
            float rel[10];
            rel[0] = pix; rel[1] = piy; rel[2] = piz;
            rel[3] = pjx; rel[4] = pjy; rel[5] = pjz;
            rel[6] = vx;  rel[7] = vy;  rel[8] = vz;
            rel[9] = sqrtf(vx*vx + vy*vy + vz*vz);

            const float4* hp = (const float4*)&g_h[(size_t)s * 32 + sub * 8];
            float4 v0 = hp[0], v1 = hp[1];
            float* dst = &fijT[(t * 64 + sub * 8) * FT1 + e];
            dst[0*FT1] = v0.x; dst[1*FT1] = v0.y; dst[2*FT1] = v0.z; dst[3*FT1] = v0.w;
            dst[4*FT1] = v1.x; dst[5*FT1] = v1.y; dst[6*FT1] = v1.z; dst[7*FT1] = v1.w;
#pragma unroll
            for (int k = 0; k < 8; k++) {
                int o = sub * 8 + k;
                float a = sbpp[o];
#pragma unroll
                for (int i = 0; i < 10; i++) a += rel[i] * sWpp[i * 32 + o];
                fijT[(t * 64 + 32 + o) * FT1 + e] = fmaxf(a, 0.f);
            }
        }
        __syncthreads();

        // ---- att = relu(fij @ Watt + batt): thread = (t8, q16, g4), full i ----
        {
            int t = tid >> 6;
            int q = (tid >> 2) & 15;
            int g = tid & 3;
            const float4* W4 = (const float4*)sWatt;
            const float* fb = &fijT[(t * 64) * FT1 + 4 * g];
            u64 acc[8];
#pragma unroll
            for (int j = 0; j < 8; j++) acc[j] = 0ull;
#pragma unroll 4
            for (int i = 0; i < 64; i++) {
                float4 w = W4[i * 16 + q];
                u64 w0 = pk1(w.x), w1 = pk1(w.y), w2 = pk1(w.z), w3 = pk1(w.w);
                ulonglong2 a = *(const ulonglong2*)(fb + i * FT1);
                acc[0] = ff2(a.x, w0, acc[0]); acc[1] = ff2(a.y, w0, acc[1]);
                acc[2] = ff2(a.x, w1, acc[2]); acc[3] = ff2(a.y, w1, acc[3]);
                acc[4] = ff2(a.x, w2, acc[4]); acc[5] = ff2(a.y, w2, acc[5]);
                acc[6] = ff2(a.x, w3, acc[6]); acc[7] = ff2(a.y, w3, acc[7]);
            }
            float* ab = &attT[(t * 64 + 4 * q) * FT1A + 4 * g];
#pragma unroll
            for (int j = 0; j < 4; j++) {
                float bb = sbatt[4*q + j];
                float2 va = upk(acc[j*2]), vb = upk(acc[j*2+1]);
                ab[j*FT1A + 0] = fmaxf(va.x + bb, 0.f);
                ab[j*FT1A + 1] = fmaxf(va.y + bb, 0.f);
                ab[j*FT1A + 2] = fmaxf(vb.x + bb, 0.f);
                ab[j*FT1A + 3] = fmaxf(vb.y + bb, 0.f);
            }
        }
        __syncthreads();

        // ---- softmax stats per edge (shfl within lane-quad) ----
        {
            int et = tid >> 2, c = tid & 3;     // 4 consecutive lanes per edge
            const float* ac = &attT[((et >> 4) * 64) * FT1A + (et & 15)];
            float m = -1e30f;
#pragma unroll 4
            for (int o = c*16; o < c*16+16; o++) m = fmaxf(m, ac[o*FT1A]);
            m = fmaxf(m, __shfl_xor_sync(0xFFFFFFFFu, m, 1));
            m = fmaxf(m, __shfl_xor_sync(0xFFFFFFFFu, m, 2));
            float s = 0.f;
#pragma unroll 4
            for (int o = c*16; o < c*16+16; o++) s += __expf(ac[o*FT1A] - m);
            s += __shfl_xor_sync(0xFFFFFFFFu, s, 1);
            s += __shfl_xor_sync(0xFFFFFFFFu, s, 2);
            if (c == 0) { sm[et] = m; sv[et] = 1.f / s; }
        }
        __syncthreads();

        // ---- agg[o] = sum_e softmax * fij ----
        {
            int t = tid >> 6, o = tid & 63;
            const float* ar = &attT[(t * 64 + o) * FT1A];
            const float* fr = &fijT[(t * 64 + o) * FT1];
            float a = 0.f;
#pragma unroll
            for (int e = 0; e < 16; e++) {
                int et = t * 16 + e;
                a += __expf(ar[e] - sm[et]) * sv[et] * fr[e];
            }
            aggS[t][o] = a;
        }
        __syncthreads();

        // ---- global: h1 = relu(agg @ Wg + bg): (t8, op32, c2), shfl pair-reduce ----
        {
            int t = tid >> 6, op = (tid >> 1) & 31, c = tid & 1;
            u64 acc = 0ull;
#pragma unroll 4
            for (int ii = 0; ii < 32; ii++) {
                int i = c * 32 + ii;
                acc = ff2(pk1(aggS[t][i]), *(const u64*)&sWg[i*64 + 2*op], acc);
            }
            u64 other = __shfl_xor_sync(0xFFFFFFFFu, acc, 1);
            acc = add2(acc, other);
            if (c == 0) {
                float2 v = upk(acc);
                int o = 2 * op;
                float* opt = &g_h1[(size_t)(t0 + t) * 64 + o];
                opt[0] = fmaxf(v.x + sbg[o],   0.f);
                opt[1] = fmaxf(v.y + sbg[o+1], 0.f);
            }
        }
        __syncthreads();
    }
}

// ---------------------------------------------------------------------------
// conv2: T=2 targets/iter, 512 threads, grid 296, occ 2. Ends at agg -> g_agg.
// fijT stride 20, attT stride 17. att i-split halves.
// ---------------------------------------------------------------------------
#define FT2  20
#define FT2A 17
#define C2_DYN_FLOATS (640 + 16384 + 2*128*FT2 + 2*128*FT2A)

__global__ void __launch_bounds__(512, 2)
conv2_kernel(const float* __restrict__ pos,
             const int*   __restrict__ idx1,
             const int*   __restrict__ idx2,
             const int*   __restrict__ src2,
             const float* __restrict__ Wpp, const float* __restrict__ bpp,
             const float* __restrict__ Watt, const float* __restrict__ batt) {
    extern __shared__ float smem[];
    float* sWpp  = smem;                        // 640
    float* sWatt = smem + 640;                  // 16384
    float* fijT  = smem + 17024;                // 2*128*20
    float* attT  = smem + 17024 + 2*128*FT2;    // 2*128*17

    __shared__ float sbpp[64], sbatt[128];
    __shared__ float sm[32], sv[32];

    int tid = threadIdx.x;
    for (int i = tid; i < 640; i += 512) sWpp[i] = Wpp[i];
    for (int i = tid; i < 16384; i += 512) sWatt[i] = Watt[i];
    if (tid < 64)  sbpp[tid] = bpp[tid];
    if (tid < 128) sbatt[tid] = batt[tid];
    __syncthreads();

    for (int t0 = blockIdx.x * 2; t0 < NN2; t0 += gridDim.x * 2) {
        // ---- gather h1[src] (0..63) + pp (64..127), transposed; rel inline ----
        {
            int et = tid >> 4, sub = tid & 15;
            int t = et >> 4, e = et & 15;
            int tgt = t0 + t;
            int pidx = idx1[idx2[tgt]];
            float pix = pos[pidx*3+0], piy = pos[pidx*3+1], piz = pos[pidx*3+2];
            int s = src2[tgt * KNN + e];
            int pj = idx1[s];
            float pjx = pos[pj*3+0], pjy = pos[pj*3+1], pjz = pos[pj*3+2];
            float vx = pix - pjx, vy = piy - pjy, vz = piz - pjz;
            float rel[10];
            rel[0] = pix; rel[1] = piy; rel[2] = piz;
            rel[3] = pjx; rel[4] = pjy; rel[5] = pjz;
            rel[6] = vx;  rel[7] = vy;  rel[8] = vz;
            rel[9] = sqrtf(vx*vx + vy*vy + vz*vz);

            float4 v = ((const float4*)&g_h1[(size_t)s * 64])[sub];
            float* dst = &fijT[(t * 128 + sub * 4) * FT2 + e];
            dst[0*FT2] = v.x; dst[1*FT2] = v.y; dst[2*FT2] = v.z; dst[3*FT2] = v.w;
#pragma unroll
            for (int k = 0; k < 4; k++) {
                int o = sub * 4 + k;
                float a = sbpp[o];
#pragma unroll
                for (int i = 0; i < 10; i++) a += rel[i] * sWpp[i * 64 + o];
                fijT[(t * 128 + 64 + o) * FT2 + e] = fmaxf(a, 0.f);
            }
        }
        __syncthreads();

        // ---- att: thread = (c2, t2, g4, q32), i-split halves ----
        {
            int c = tid >> 8;
            int t = (tid >> 7) & 1;
            int g = (tid >> 5) & 3;
            int q = tid & 31;
            const float4* W4 = (const float4*)sWatt;
            const float* fb = &fijT[(t * 128) * FT2 + 4 * g];
            u64 acc[8];
#pragma unroll
            for (int j = 0; j < 8; j++) acc[j] = 0ull;
#pragma unroll 4
            for (int ii = 0; ii < 64; ii++) {
                int i = c * 64 + ii;
                float4 w = W4[i * 32 + q];
                u64 w0 = pk1(w.x), w1 = pk1(w.y), w2 = pk1(w.z), w3 = pk1(w.w);
                ulonglong2 a = *(const ulonglong2*)(fb + i * FT2);
                acc[0] = ff2(a.x, w0, acc[0]); acc[1] = ff2(a.y, w0, acc[1]);
                acc[2] = ff2(a.x, w1, acc[2]); acc[3] = ff2(a.y, w1, acc[3]);
                acc[4] = ff2(a.x, w2, acc[4]); acc[5] = ff2(a.y, w2, acc[5]);
                acc[6] = ff2(a.x, w3, acc[6]); acc[7] = ff2(a.y, w3, acc[7]);
            }
            float* ab = &attT[(t * 128 + 4 * q) * FT2A + 4 * g];
            if (c == 1) {
#pragma unroll
                for (int j = 0; j < 4; j++) {
                    float2 va = upk(acc[j*2]), vb = upk(acc[j*2+1]);
                    ab[j*FT2A + 0] = va.x; ab[j*FT2A + 1] = va.y;
                    ab[j*FT2A + 2] = vb.x; ab[j*FT2A + 3] = vb.y;
                }
            }
            __syncthreads();
            if (c == 0) {
#pragma unroll
                for (int j = 0; j < 4; j++) {
                    float bb = sbatt[4*q + j];
                    float2 va = upk(acc[j*2]), vb = upk(acc[j*2+1]);
                    ab[j*FT2A + 0] = fmaxf(ab[j*FT2A + 0] + va.x + bb, 0.f);
                    ab[j*FT2A + 1] = fmaxf(ab[j*FT2A + 1] + va.y + bb, 0.f);
                    ab[j*FT2A + 2] = fmaxf(ab[j*FT2A + 2] + vb.x + bb, 0.f);
                    ab[j*FT2A + 3] = fmaxf(ab[j*FT2A + 3] + vb.y + bb, 0.f);
                }
            }
            __syncthreads();
        }

        // ---- softmax per edge over 128 features (shfl over 16 lanes) ----
        {
            int et = tid >> 4, cc = tid & 15;   // 16 consecutive lanes per edge
            const float* ac = &attT[((et >> 4) * 128) * FT2A + (et & 15)];
            float m = -1e30f;
#pragma unroll
            for (int o = cc*8; o < cc*8+8; o++) m = fmaxf(m, ac[o*FT2A]);
            m = fmaxf(m, __shfl_xor_sync(0xFFFFFFFFu, m, 1));
            m = fmaxf(m, __shfl_xor_sync(0xFFFFFFFFu, m, 2));
            m = fmaxf(m, __shfl_xor_sync(0xFFFFFFFFu, m, 4));
            m = fmaxf(m, __shfl_xor_sync(0xFFFFFFFFu, m, 8));
            float s = 0.f;
#pragma unroll
            for (int o = cc*8; o < cc*8+8; o++) s += __expf(ac[o*FT2A] - m);
            s += __shfl_xor_sync(0xFFFFFFFFu, s, 1);
            s += __shfl_xor_sync(0xFFFFFFFFu, s, 2);
            s += __shfl_xor_sync(0xFFFFFFFFu, s, 4);
            s += __shfl_xor_sync(0xFFFFFFFFu, s, 8);
            if (cc == 0) { sm[et] = m; sv[et] = 1.f / s; }
        }
        __syncthreads();

        // ---- agg -> global scratch ----
        if (tid < 256) {
            int t = tid >> 7, o = tid & 127;
            const float* ar = &attT[(t * 128 + o) * FT2A];
            const float* fr = &fijT[(t * 128 + o) * FT2];
            float a = 0.f;
#pragma unroll
            for (int e = 0; e < 16; e++) {
                int et = t * 16 + e;
                a += __expf(ar[e] - sm[et]) * sv[et] * fr[e];
            }
            g_agg[(size_t)(t0 + t) * 128 + o] = a;
        }
        __syncthreads();
    }
}

// ---------------------------------------------------------------------------
// gemm2: h2 = relu(g_agg @ Wg + bg). T=32 targets/iter, thread=(tg16,q32)x2tgt.
// 512 threads, grid 296, occ 2. Weight LDS.128 reused across 2 targets.
// ---------------------------------------------------------------------------
#define G2_DYN_FLOATS (128*128 + 32*128)

__global__ void __launch_bounds__(512, 2)
gemm2_kernel(const float* __restrict__ Wg, const float* __restrict__ bg) {
    extern __shared__ float smem[];
    float* sWg  = smem;                 // 16384
    float* sagg = smem + 16384;         // 32*128
    __shared__ float sbg[128];

    int tid = threadIdx.x;
    for (int i = tid; i < 16384; i += 512) sWg[i] = Wg[i];
    if (tid < 128) sbg[tid] = bg[tid];
    __syncthreads();

    for (int t0 = blockIdx.x * 32; t0 < NN2; t0 += gridDim.x * 32) {
#pragma unroll
        for (int k = 0; k < 8; k++)
            sagg[tid + 512*k] = g_agg[(size_t)t0 * 128 + tid + 512*k];
        __syncthreads();

        int tg = tid >> 5;             // 16 groups, 2 targets each
        int q  = tid & 31;             // 4 outputs
        const float* a0p = &sagg[(2*tg + 0) * 128];
        const float* a1p = &sagg[(2*tg + 1) * 128];
        const float4* W4 = (const float4*)sWg;

        u64 acc[4];
#pragma unroll
        for (int j = 0; j < 4; j++) acc[j] = 0ull;
#pragma unroll 4
        for (int i = 0; i < 128; i++) {
            float4 w = W4[i * 32 + q];
            u64 wlo = pk2(w.x, w.y), whi = pk2(w.z, w.w);
            u64 x0 = pk1(a0p[i]), x1 = pk1(a1p[i]);
            acc[0] = ff2(x0, wlo, acc[0]); acc[1] = ff2(x0, whi, acc[1]);
            acc[2] = ff2(x1, wlo, acc[2]); acc[3] = ff2(x1, whi, acc[3]);
        }
        int o = 4 * q;
        u64 bb0 = pk2(sbg[o], sbg[o+1]), bb1 = pk2(sbg[o+2], sbg[o+3]);
#pragma unroll
        for (int tt = 0; tt < 2; tt++) {
            float2 v0 = upk(add2(acc[tt*2],   bb0));
            float2 v1 = upk(add2(acc[tt*2+1], bb1));
            float* op = &g_h2[(size_t)(t0 + 2*tg + tt) * 128 + o];
            op[0] = fmaxf(v0.x, 0.f);
            op[1] = fmaxf(v0.y, 0.f);
            op[2] = fmaxf(v1.x, 0.f);
            op[3] = fmaxf(v1.y, 0.f);
        }
        __syncthreads();
    }
}

// ---------------------------------------------------------------------------
// tail: T=16 targets/iter, thread=(tg8,op64)x2 targets. 512 threads, grid 296.
// ---------------------------------------------------------------------------
#define TAIL_DYN_FLOATS (128*128 + 64*128 + 16*128 + 16*64)

__global__ void __launch_bounds__(512, 2)
tail_kernel(const float* __restrict__ x,
            const int*   __restrict__ idx1,
            const int*   __restrict__ idx2,
            const float* __restrict__ Wup, const float* __restrict__ bup,
            const float* __restrict__ Wsc, const float* __restrict__ bsc,
            float* __restrict__ out) {
    extern __shared__ float smem[];
    float* sWup = smem;                       // 16384
    float* sWsc = smem + 16384;               // 8192
    float* sh2  = smem + 24576;               // 16*128
    float* sx   = smem + 24576 + 16*128;      // 16*64

    __shared__ float sbup[128], sbsc[128];

    int tid = threadIdx.x;
    for (int i = tid; i < 16384; i += 512) sWup[i] = Wup[i];
    for (int i = tid; i < 8192;  i += 512) sWsc[i] = Wsc[i];
    if (tid < 128) { sbup[tid] = bup[tid]; sbsc[tid] = bsc[tid]; }
    __syncthreads();

    for (int t0 = blockIdx.x * 16; t0 < NN2; t0 += gridDim.x * 16) {
#pragma unroll
        for (int k = 0; k < 4; k++)
            sh2[tid + 512*k] = g_h2[(size_t)t0 * 128 + tid + 512*k];
        {
            int t = tid >> 5, f2 = tid & 31;
            int xr = idx1[idx2[t0 + t]];
            const float2* xp = (const float2*)&x[(size_t)xr * 64];
            ((float2*)&sx[t * 64])[f2] = xp[f2];
        }
        __syncthreads();

        int tg = tid >> 6;             // 8 groups, 2 targets each
        int op = tid & 63;             // 2 outputs
        const float* h0 = &sh2[(2*tg + 0) * 128];
        const float* h1 = &sh2[(2*tg + 1) * 128];
        const float* x0 = &sx[(2*tg + 0) * 64];
        const float* x1 = &sx[(2*tg + 1) * 64];

        u64 u0 = 0ull, u1 = 0ull;
#pragma unroll 4
        for (int i = 0; i < 128; i++) {
            u64 w = *(const u64*)&sWup[i*128 + 2*op];
            u0 = ff2(pk1(h0[i]), w, u0);
            u1 = ff2(pk1(h1[i]), w, u1);
        }
        u64 s0 = 0ull, s1 = 0ull;
#pragma unroll 4
        for (int i = 0; i < 64; i++) {
            u64 w = *(const u64*)&sWsc[i*128 + 2*op];
            s0 = ff2(pk1(x0[i]), w, s0);
            s1 = ff2(pk1(x1[i]), w, s1);
        }
        int o = 2 * op;
        float bu0 = sbup[o], bu1 = sbup[o+1];
        float bs0 = sbsc[o], bs1 = sbsc[o+1];
        {
            float2 a = upk(u0), c = upk(s0);
            float* opt = &out[(size_t)(t0 + 2*tg) * 128 + o];
            opt[0] = fmaxf(fmaxf(a.x + bu0, 0.f) + fmaxf(c.x + bs0, 0.f), 0.f);
            opt[1] = fmaxf(fmaxf(a.y + bu1, 0.f) + fmaxf(c.y + bs1, 0.f), 0.f);
        }
        {
            float2 a = upk(u1), c = upk(s1);
            float* opt = &out[(size_t)(t0 + 2*tg + 1) * 128 + o];
            opt[0] = fmaxf(fmaxf(a.x + bu0, 0.f) + fmaxf(c.x + bs0, 0.f), 0.f);
            opt[1] = fmaxf(fmaxf(a.y + bu1, 0.f) + fmaxf(c.y + bs1, 0.f), 0.f);
        }
        __syncthreads();
    }
}

// ---------------------------------------------------------------------------
extern "C" void kernel_launch(void* const* d_in, const int* in_sizes, int n_in,
                              void* d_out, int out_size) {
    const float* x      = (const float*)d_in[0];
    const float* pos    = (const float*)d_in[1];
    const float* W_down = (const float*)d_in[2];
    const float* b_down = (const float*)d_in[3];
    const float* W_pp1  = (const float*)d_in[4];
    const float* b_pp1  = (const float*)d_in[5];
    const float* W_att1 = (const float*)d_in[6];
    const float* b_att1 = (const float*)d_in[7];
    const float* W_g1   = (const float*)d_in[8];
    const float* b_g1   = (const float*)d_in[9];
    const float* W_pp2  = (const float*)d_in[10];
    const float* b_pp2  = (const float*)d_in[11];
    const float* W_att2 = (const float*)d_in[12];
    const float* b_att2 = (const float*)d_in[13];
    const float* W_g2   = (const float*)d_in[14];
    const float* b_g2   = (const float*)d_in[15];
    const float* W_up   = (const float*)d_in[16];
    const float* b_up   = (const float*)d_in[17];
    const float* W_sc   = (const float*)d_in[18];
    const float* b_sc   = (const float*)d_in[19];
    const int*   idx1   = (const int*)d_in[20];
    const int*   idx2   = (const int*)d_in[21];
    const int*   src1   = (const int*)d_in[22];
    const int*   src2   = (const int*)d_in[24];
    float* out = (float*)d_out;

    cudaFuncSetAttribute(conv1_kernel, cudaFuncAttributeMaxDynamicSharedMemorySize,
                         C1_DYN_FLOATS * (int)sizeof(float));
    cudaFuncSetAttribute(conv2_kernel, cudaFuncAttributeMaxDynamicSharedMemorySize,
                         C2_DYN_FLOATS * (int)sizeof(float));
    cudaFuncSetAttribute(gemm2_kernel, cudaFuncAttributeMaxDynamicSharedMemorySize,
                         G2_DYN_FLOATS * (int)sizeof(float));
    cudaFuncSetAttribute(tail_kernel, cudaFuncAttributeMaxDynamicSharedMemorySize,
                         TAIL_DYN_FLOATS * (int)sizeof(float));

    down_kernel<<<NPTS / 256, 256>>>(x, W_down, b_down);
    conv1_kernel<<<296, 512, C1_DYN_FLOATS * sizeof(float)>>>(
        pos, idx1, src1, W_pp1, b_pp1, W_att1, b_att1, W_g1, b_g1);
    conv2_kernel<<<296, 512, C2_DYN_FLOATS * sizeof(float)>>>(
        pos, idx1, idx2, src2, W_pp2, b_pp2, W_att2, b_att2);
    gemm2_kernel<<<296, 512, G2_DYN_FLOATS * sizeof(float)>>>(W_g2, b_g2);
    tail_kernel<<<296, 512, TAIL_DYN_FLOATS * sizeof(float)>>>(
        x, idx1, idx2, W_up, b_up, W_sc, b_sc, out);
}